// round 10
// baseline (speedup 1.0000x reference)
#include <cuda_runtime.h>

#define L_SEQ 1024
#define M_DIM 128

// Final table, step-major, padded two steps (prefetch depth 2):
//   per step i: floats [0..127]   W[m] = dlt[m,i] * P0[m,i]   (P0 = prod_{j<i} e0[m,j])
//               floats [128..255] q[m] = dlt[m,i] / e0[m,i]
__device__ float g_tbl[(L_SEQ + 2) * 256];
__device__ float g_e0[L_SEQ * M_DIM];
__device__ float g_dl[L_SEQ * M_DIM];
__device__ float g_cp[8 * M_DIM];

typedef unsigned long long u64;

__device__ __forceinline__ u64 pk2(float lo, float hi) {
    u64 r; asm("mov.b64 %0,{%1,%2};" : "=l"(r) : "f"(lo), "f"(hi)); return r;
}
__device__ __forceinline__ void upk2(u64 v, float& lo, float& hi) {
    asm("mov.b64 {%0,%1},%2;" : "=f"(lo), "=f"(hi) : "l"(v));
}
__device__ __forceinline__ u64 fma2(u64 a, u64 b, u64 c) {
    u64 r; asm("fma.rn.f32x2 %0,%1,%2,%3;" : "=l"(r) : "l"(a), "l"(b), "l"(c)); return r;
}
__device__ __forceinline__ u64 mul2(u64 a, u64 b) {
    u64 r; asm("mul.rn.f32x2 %0,%1,%2;" : "=l"(r) : "l"(a), "l"(b)); return r;
}
__device__ __forceinline__ u64 add2(u64 a, u64 b) {
    u64 r; asm("add.rn.f32x2 %0,%1,%2;" : "=l"(r) : "l"(a), "l"(b)); return r;
}
// predicated: if (s) { h0 = q0*h0 + h0; h1 = q1*h1 + h1; }
__device__ __forceinline__ void upd2(u64& h0, u64& h1, u64 q0, u64 q1, int s) {
    asm("{.reg .pred P; setp.ne.s32 P,%4,0;"
        "@P fma.rn.f32x2 %0,%2,%0,%0;"
        "@P fma.rn.f32x2 %1,%3,%1,%1;}"
        : "+l"(h0), "+l"(h1) : "l"(q0), "l"(q1), "r"(s));
}

// prepA: transpose eps [D,M,L] -> step-major e0 / dlt
__global__ void prepA(const float* __restrict__ eps) {
    int idx = blockIdx.x * blockDim.x + threadIdx.x;
    if (idx >= L_SEQ * M_DIM) return;
    int i = idx >> 7, m = idx & 127;
    float a = eps[(size_t)m * L_SEQ + i];
    float b = eps[(size_t)(M_DIM + m) * L_SEQ + i];
    g_e0[i * 128 + m] = a;
    g_dl[i * 128 + m] = b - a;
}

// prepB: per (m, chunk c of 128 steps) product of e0
__global__ void prepB() {
    int idx = blockIdx.x * blockDim.x + threadIdx.x;   // 0..1023
    int m = idx & 127, c = idx >> 7;
    float p = 1.f;
    #pragma unroll 8
    for (int t = 0; t < 128; t++)
        p *= g_e0[(c * 128 + t) * 128 + m];
    g_cp[c * 128 + m] = p;
}

// prepC: scan within chunk, write W and q; zero the 2 pad steps
__global__ void prepC() {
    int idx = blockIdx.x * blockDim.x + threadIdx.x;   // 0..1023
    int m = idx & 127, c = idx >> 7;
    float P = 1.f;
    for (int cc = 0; cc < c; cc++) P *= g_cp[cc * 128 + m];
    for (int t = 0; t < 128; t++) {
        int i = c * 128 + t;
        float e = g_e0[i * 128 + m];
        float d = g_dl[i * 128 + m];
        g_tbl[i * 256 + m]       = d * P;
        g_tbl[i * 256 + 128 + m] = __fdividef(d, e);
        P *= e;
    }
    if (c == 0) {
        g_tbl[L_SEQ * 256 + m] = 0.f;       g_tbl[L_SEQ * 256 + 128 + m] = 0.f;
        g_tbl[(L_SEQ + 1) * 256 + m] = 0.f; g_tbl[(L_SEQ + 1) * 256 + 128 + m] = 0.f;
    }
}

#define WIN 16                 // window (steps) between smem reductions
#define ST 33                  // u64 stride per step (>=32: no overlap; odd: bank spread)
#define A1OFF 552              // array1 base (>= WIN*ST=528, and 552 % 32 == 8 -> opposite bank half)
#define WBUF 1080              // per-warp u64 buffer (two arrays)

__global__ __launch_bounds__(128)
void arqgps_kernel(const int* __restrict__ inp, float* __restrict__ out, int nrows) {
    __shared__ u64 sp[4][WBUF];                       // 4 warps x 8640 B = 34.6 KB
    const unsigned FULL = 0xffffffffu;
    const int lane = threadIdx.x & 31;
    const int wid  = threadIdx.x >> 5;
    const int nrg  = nrows >> 2;                      // 4 rows per warp
    const int rg_raw = blockIdx.x * 4 + wid;
    const bool live = (rg_raw < nrg);
    const int rg = live ? rg_raw : (nrg - 1);         // clamp; never early-exit (ballots!)

    const ulonglong2* __restrict__ tb = reinterpret_cast<const ulonglong2*>(g_tbl);
    const int* __restrict__ p0r = inp + (size_t)(4 * rg) * L_SEQ;
    const int* __restrict__ p1r = p0r + L_SEQ;
    const int* __restrict__ p2r = p1r + L_SEQ;
    const int* __restrict__ p3r = p2r + L_SEQ;

    const u64 one2 = pk2(1.f, 1.f);
    u64 HA[2] = {one2, one2}, HB[2] = {one2, one2};   // rows 0,1 (4 m each)
    u64 HC[2] = {one2, one2}, HD[2] = {one2, one2};   // rows 2,3

    // read-phase identity: this lane finalizes (row = lane>>3, steps (lane&7), (lane&7)+8)
    const int myrow = lane >> 3;
    const int kb    = lane & 7;

    u64* const wp0 = &sp[wid][0];                     // pair(0,1) partials
    u64* const wp1 = &sp[wid][A1OFF];                 // pair(2,3) partials
    const u64* const rp = (myrow & 2) ? wp1 : wp0;    // my row's array

    float acc = 0.f;
    int   c1m = 0;                                    // 1-count for MY row before window

    // depth-2 tile pipeline
    ulonglong2 Wc = tb[lane],      Qc = tb[32 + lane];
    ulonglong2 Wn = tb[64 + lane], Qn = tb[96 + lane];

    unsigned b0 = __ballot_sync(FULL, __ldg(p0r + lane) & 1);
    unsigned b1 = __ballot_sync(FULL, __ldg(p1r + lane) & 1);
    unsigned b2 = __ballot_sync(FULL, __ldg(p2r + lane) & 1);
    unsigned b3 = __ballot_sync(FULL, __ldg(p3r + lane) & 1);
    unsigned mybits = (myrow & 2) ? ((myrow & 1) ? b3 : b2) : ((myrow & 1) ? b1 : b0);

    for (int i0 = 0; i0 < L_SEQ; i0 += 32) {
        const int nx = i0 + 32;
        const bool more = (nx < L_SEQ);
        const unsigned n0 = __ballot_sync(FULL, (more ? __ldg(p0r + nx + lane) : 0) & 1);
        const unsigned n1 = __ballot_sync(FULL, (more ? __ldg(p1r + nx + lane) : 0) & 1);
        const unsigned n2 = __ballot_sync(FULL, (more ? __ldg(p2r + nx + lane) : 0) & 1);
        const unsigned n3 = __ballot_sync(FULL, (more ? __ldg(p3r + nx + lane) : 0) & 1);
        const ulonglong2* __restrict__ bb = tb + (size_t)i0 * 64;

        #pragma unroll
        for (int h = 0; h < 2; h++) {
            // ---- write phase: 16 steps ----
            #pragma unroll
            for (int t = 0; t < WIN; t++) {
                const int k = h * WIN + t;
                ulonglong2 W2 = bb[(size_t)(k + 2) * 64 + lane];
                ulonglong2 Q2 = bb[(size_t)(k + 2) * 64 + 32 + lane];

                u64 pA = fma2(Wc.y, HA[1], mul2(Wc.x, HA[0]));
                u64 pB = fma2(Wc.y, HB[1], mul2(Wc.x, HB[0]));
                u64 pC = fma2(Wc.y, HC[1], mul2(Wc.x, HC[0]));
                u64 pD = fma2(Wc.y, HD[1], mul2(Wc.x, HD[0]));

                upd2(HA[0], HA[1], Qc.x, Qc.y, (int)((b0 >> k) & 1u));
                upd2(HB[0], HB[1], Qc.x, Qc.y, (int)((b1 >> k) & 1u));
                upd2(HC[0], HC[1], Qc.x, Qc.y, (int)((b2 >> k) & 1u));
                upd2(HD[0], HD[1], Qc.x, Qc.y, (int)((b3 >> k) & 1u));

                float a0, a1, c0, c1, e0, e1, f0, f1;
                upk2(pA, a0, a1); upk2(pB, c0, c1);
                upk2(pC, e0, e1); upk2(pD, f0, f1);
                wp0[t * ST + lane] = pk2(a0 + a1, c0 + c1);   // (row0, row1)
                wp1[t * ST + lane] = pk2(e0 + e1, f0 + f1);   // (row2, row3)

                Wc = Wn; Qc = Qn; Wn = W2; Qn = Q2;
            }
            __syncwarp();

            // ---- read phase: 2 steps per lane (kb and kb+8), my row only ----
            const unsigned bw = (mybits >> (h * WIN)) & 0xffffu;
            #pragma unroll
            for (int pass = 0; pass < 2; pass++) {
                const int kk = kb + 8 * pass;
                const u64* rb = rp + kk * ST;
                u64 s0 = rb[0], s1 = rb[1], s2 = rb[2], s3 = rb[3];
                #pragma unroll
                for (int l = 4; l < 32; l += 4) {
                    s0 = add2(s0, rb[l]);
                    s1 = add2(s1, rb[l + 1]);
                    s2 = add2(s2, rb[l + 2]);
                    s3 = add2(s3, rb[l + 3]);
                }
                u64 st = add2(add2(s0, s1), add2(s2, s3));
                float dr0, dr1; upk2(st, dr0, dr1);
                const float dxt = (myrow & 1) ? dr1 : dr0;

                const int s   = (int)((bw >> kk) & 1u);
                const int c1i = c1m + __popc(bw & ((1u << kk) - 1u));
                const int i   = i0 + h * WIN + kk;

                const float sgn = s ? dxt : -dxt;
                const float contrib = fminf(0.f, sgn)
                                    - 0.5f * __logf(1.f + __expf(-2.f * fabsf(dxt)));
                const bool dead_other = s ? ((i - c1i) >= 512) : (c1i >= 512);
                acc += dead_other ? 0.f : contrib;
            }
            c1m += __popc(bw);
            __syncwarp();                            // next window's writers wait for readers
        }

        b0 = n0; b1 = n1; b2 = n2; b3 = n3;
        mybits = (myrow & 2) ? ((myrow & 1) ? b3 : b2) : ((myrow & 1) ? b1 : b0);
    }

    // sum acc across the 8 lanes owning each row (xor < 8 stays inside row group)
    acc += __shfl_xor_sync(FULL, acc, 1);
    acc += __shfl_xor_sync(FULL, acc, 2);
    acc += __shfl_xor_sync(FULL, acc, 4);

    if (live && kb == 0) out[4 * rg + myrow] = acc;
}

extern "C" void kernel_launch(void* const* d_in, const int* in_sizes, int n_in,
                              void* d_out, int out_size) {
    const int*   inp = nullptr;
    const float* eps = nullptr;
    int rows = 0;
    if (in_sizes[0] == 2 * M_DIM * L_SEQ) {
        eps = (const float*)d_in[0];
        inp = (const int*)d_in[1];
        rows = in_sizes[1] / L_SEQ;
    } else {
        inp = (const int*)d_in[0];
        eps = (const float*)d_in[1];
        rows = in_sizes[0] / L_SEQ;
    }

    { int n = L_SEQ * M_DIM; prepA<<<(n + 255) / 256, 256>>>(eps); }
    prepB<<<4, 256>>>();
    prepC<<<4, 256>>>();
    {
        // one warp per 4 rows; 4 warps (16 rows) per 128-thread block
        int nrg = rows / 4;
        int grid = (nrg + 3) / 4;
        arqgps_kernel<<<grid, 128>>>(inp, (float*)d_out, rows);
    }
}